// round 2
// baseline (speedup 1.0000x reference)
#include <cuda_runtime.h>

#define B 4
#define S 128
#define SS (S*S)
#define BSS (B*S*S)

// q matrices (row-major) and their transposes, per batch.
__device__ __align__(16) float g_qb[BSS], g_qe[BSS], g_qs[BSS];
__device__ __align__(16) float g_qbT[BSS], g_qeT[BSS], g_qsT[BSS];

// normalized masks (uint8 0/1) + detected source dtype modes
__device__ unsigned char g_edge[BSS];
__device__ unsigned char g_chart[BSS];
__device__ int g_mode_e, g_mode_c;   // 0=uint8, 1=int32, 2=float32

// ---------------------------------------------------------------------------
// dtype sniffing: bool masks may arrive as uint8, int32, or float32.
// int32 0/1 data -> every word in {0,1}. float32 -> {0, 0x3f800000}.
// packed uint8 0/1 -> words like 0x00010001 (neither set, w.h.p.).
// ---------------------------------------------------------------------------
__global__ void k_detect(const unsigned int* __restrict__ me,
                         const unsigned int* __restrict__ mc)
{
    bool a01 = true, af = true;
    for (int w = 0; w < 64; ++w) {
        unsigned v = me[w];
        if (v != 0u && v != 1u) a01 = false;
        if (v != 0u && v != 0x3f800000u) af = false;
    }
    g_mode_e = a01 ? 1 : (af ? 2 : 0);
    a01 = true; af = true;
    for (int w = 0; w < 64; ++w) {
        unsigned v = mc[w];
        if (v != 0u && v != 1u) a01 = false;
        if (v != 0u && v != 0x3f800000u) af = false;
    }
    g_mode_c = a01 ? 1 : (af ? 2 : 0);
}

__global__ void k_convert(const unsigned char* __restrict__ se,
                          const unsigned char* __restrict__ sc)
{
    int i = blockIdx.x * blockDim.x + threadIdx.x;
    if (i >= BSS) return;
    int me = g_mode_e, mc = g_mode_c;
    unsigned char ve, vc;
    if (me == 1)      ve = (((const int*)se)[i]   != 0);
    else if (me == 2) ve = (((const float*)se)[i] != 0.f);
    else              ve = (se[i] != 0);
    if (mc == 1)      vc = (((const int*)sc)[i]   != 0);
    else if (mc == 2) vc = (((const float*)sc)[i] != 0.f);
    else              vc = (sc[i] != 0);
    g_edge[i]  = ve;
    g_chart[i] = vc;
}

// ---------------------------------------------------------------------------
// init: out = [s_arg_begin | s_arg_end | s_const]
// ---------------------------------------------------------------------------
__global__ void k_init(const float* __restrict__ sb, const float* __restrict__ se,
                       const float* __restrict__ sc, float* __restrict__ out)
{
    int idx = blockIdx.x * blockDim.x + threadIdx.x;
    if (idx < BSS) {
        out[idx]         = sb[idx];
        out[BSS + idx]   = se[idx];
        out[2*BSS + idx] = sc[idx];
    }
}

// ---------------------------------------------------------------------------
// sigmoid: q* = sigmoid(base*), plus transposed copies for coalesced access.
// ---------------------------------------------------------------------------
__global__ void k_sigmoid(const float* __restrict__ out)
{
    int idx = blockIdx.x * blockDim.x + threadIdx.x;
    if (idx >= BSS) return;
    int b = idx / SS;
    int r = (idx / S) & (S - 1);
    int c = idx & (S - 1);
    int tidx = (b * S + c) * S + r;

    float vb = 1.f / (1.f + __expf(-out[idx]));
    float ve = 1.f / (1.f + __expf(-out[BSS + idx]));
    float vs = 1.f / (1.f + __expf(-out[2*BSS + idx]));
    g_qb[idx] = vb;  g_qbT[tidx] = vb;
    g_qe[idx] = ve;  g_qeT[tidx] = ve;
    g_qs[idx] = vs;  g_qsT[tidx] = vs;
}

// ---------------------------------------------------------------------------
// k_main: block = (b, i). All terms consumed in natural [b,i,j,k] row order,
// plus span_grd_b (layout [b,k,i,j], also (b,i)-sliced).
// ---------------------------------------------------------------------------
__global__ void __launch_bounds__(256) k_main(
    const float* __restrict__ t_be, const float* __restrict__ t_eb,
    const float* __restrict__ t_bb, const float* __restrict__ t_ee,
    const float* __restrict__ t_cb, const float* __restrict__ t_ce,
    const float* __restrict__ t_gb, const float* __restrict__ t_ge,
    const float* __restrict__ t_sp,
    float* __restrict__ out)
{
    const int b    = blockIdx.x >> 7;
    const int i    = blockIdx.x & 127;
    const int tid  = threadIdx.x;
    const int lane = tid & 31;
    const int warp = tid >> 5;

    __shared__ unsigned char sm_e[S];    // edge[b,i,:]
    __shared__ unsigned char sm_ch[S];   // chart[b,i,:] = chart_mask[b,(i-1)%S,:]
    __shared__ unsigned char sm_c0[S];   // chart_mask[b,0,:]
    __shared__ float sm_qb[S], sm_qe[S], sm_qs[S], sm_qbT[S];
    __shared__ float sm_ab[S], sm_ae[S], sm_as[S];
    __shared__ float sm_span[256];

    if (tid < S) {
        sm_e[tid]  = g_edge[(b*S + i)*S + tid];
        sm_ch[tid] = g_chart[(b*S + ((i + S - 1) & 127))*S + tid];
        sm_c0[tid] = g_chart[b*SS + tid];
        int q = (b*S + i)*S + tid;
        sm_qb[tid]  = g_qb[q];
        sm_qe[tid]  = g_qe[q];
        sm_qs[tid]  = g_qs[q];
        sm_qbT[tid] = g_qbT[q];
    }
    __syncthreads();

    // ---- phase 1: one warp per j-row, float4 (4 k's) per lane ----
    for (int j = warp; j < S; j += 8) {
        const bool ej = (sm_e[j] != 0);
        const bool sp = (sm_ch[j] != 0) && (sm_c0[j] != 0);
        float ab = 0.f, ae = 0.f, as_ = 0.f;

        const int k0     = lane * 4;
        const int rowoff = ((b*S + i)*S + j)*S + k0;
        const int qoff   = (b*S + j)*S + k0;

        if (ej) {
            float a_be[4], a_eb[4], a_bb[4], a_ee[4];
            float a_cb[4], a_ce[4], a_gb[4], a_ge[4];
            float qbTj[4], qeTj[4], qsj[4], qsTj[4];
            *(float4*)a_be = *(const float4*)(t_be + rowoff);
            *(float4*)a_eb = *(const float4*)(t_eb + rowoff);
            *(float4*)a_bb = *(const float4*)(t_bb + rowoff);
            *(float4*)a_ee = *(const float4*)(t_ee + rowoff);
            *(float4*)a_cb = *(const float4*)(t_cb + rowoff);
            *(float4*)a_ce = *(const float4*)(t_ce + rowoff);
            *(float4*)a_gb = *(const float4*)(t_gb + rowoff);
            *(float4*)a_ge = *(const float4*)(t_ge + rowoff);
            *(float4*)qbTj = *(const float4*)(g_qbT + qoff);
            *(float4*)qeTj = *(const float4*)(g_qeT + qoff);
            *(float4*)qsj  = *(const float4*)(g_qs  + qoff);
            *(float4*)qsTj = *(const float4*)(g_qsT + qoff);

            const float m_sw_row = (i != j) ? 1.f : 0.f;  // (i!=j), row-level
            #pragma unroll
            for (int u = 0; u < 4; ++u) {
                const int k = k0 + u;
                const float e_ik = sm_e[k] ? 1.f : 0.f;
                const float m_wm = (i != k) ? e_ik : 0.f;                           // mask2o_wm
                const float m_2o = (j != k) ? m_wm : 0.f;                           // mask2o
                const float m_nc = (j <= k && (j >= i || k <= i)) ? m_wm : 0.f;     // noncross
                const float m_sw = m_sw_row * e_ik;                                 // wm swapped
                const float m_ns = (k <= j && (k >= i || j <= i)) ? m_sw : 0.f;     // noncross swapped

                ab += m_wm * sm_qe[k] * a_be[u]
                    + m_2o * (sm_qb[k] * a_bb[u] + qbTj[u] * a_cb[u])
                    + m_nc * qsj[u] * a_gb[u];
                ae += m_sw * sm_qb[k] * a_eb[u]
                    + m_2o * (sm_qe[k] * a_ee[u] + qeTj[u] * a_ce[u])
                    + m_ns * qsTj[u] * a_ge[u];
            }
        }
        if (sp) {
            float a_sp[4];
            *(float4*)a_sp = *(const float4*)(t_sp + rowoff);
            const int mx = (i > j) ? i : j;
            #pragma unroll
            for (int u = 0; u < 4; ++u) {
                const int k = k0 + u;
                const float m = (sm_c0[k] && k != mx) ? 1.f : 0.f;
                as_ += m * sm_qs[k] * a_sp[u];
            }
        }
        #pragma unroll
        for (int o = 16; o; o >>= 1) {
            ab  += __shfl_xor_sync(0xffffffffu, ab,  o);
            ae  += __shfl_xor_sync(0xffffffffu, ae,  o);
            as_ += __shfl_xor_sync(0xffffffffu, as_, o);
        }
        if (lane == 0) { sm_ab[j] = ab; sm_ae[j] = ae; sm_as[j] = as_; }
    }
    __syncthreads();

    // ---- phase 2: span_grd_b — base_s[b,i,j] += sum_k qb[b,k,i]*grd_b[b,k,i,j]*outside ----
    {
        const int j  = tid & 127;
        const int kh = tid >> 7;
        float acc = 0.f;
        const bool rowon = (sm_ch[j] != 0) && (sm_c0[j] != 0);
        if (rowon) {
            const int mx = (i > j) ? i : j;
            #pragma unroll 4
            for (int k = kh * 64; k < kh * 64 + 64; ++k) {
                if (!sm_c0[k]) continue;
                const bool m = !((i <= k) && (j >= k)) && (mx != k);
                if (m)
                    acc += sm_qbT[k] * t_gb[((b*S + k)*S + i)*S + j];
            }
        }
        sm_span[tid] = acc;
    }
    __syncthreads();

    if (tid < S) {
        const int o = (b*S + i)*S + tid;
        out[o]         += sm_ab[tid];
        out[BSS + o]   += sm_ae[tid];
        out[2*BSS + o] += sm_as[tid] + sm_span[tid] + sm_span[tid + 128];
    }
}

// ---------------------------------------------------------------------------
// k_spanE: block = (b, j). base_s[b,i,j] += sum_k qe[b,k,j]*grd_e[b,k,j,i]*outside
// ---------------------------------------------------------------------------
__global__ void __launch_bounds__(256) k_spanE(
    const float* __restrict__ t_ge,
    float* __restrict__ out)
{
    const int b = blockIdx.x >> 7;
    const int j = blockIdx.x & 127;
    const int tid = threadIdx.x;

    __shared__ unsigned char sm_c0[S];
    __shared__ unsigned char sm_chc[S];  // chart[b,i,j] over i
    __shared__ float sm_qeT[S];
    __shared__ float sm_acc[256];

    if (tid < S) {
        sm_c0[tid]  = g_chart[b*SS + tid];
        sm_chc[tid] = g_chart[(b*S + ((tid + S - 1) & 127))*S + j];
        sm_qeT[tid] = g_qeT[(b*S + j)*S + tid];
    }
    __syncthreads();
    if (!sm_c0[j]) return;   // pad factor c0[b,j] kills the whole block (uniform)

    const int i  = tid & 127;
    const int kh = tid >> 7;
    float acc = 0.f;
    if (sm_chc[i]) {
        const int mx = (i > j) ? i : j;
        #pragma unroll 4
        for (int k = kh * 64; k < kh * 64 + 64; ++k) {
            if (!sm_c0[k]) continue;
            const bool m = !((i <= k) && (j >= k)) && (mx != k);
            if (m)
                acc += sm_qeT[k] * t_ge[((b*S + k)*S + j)*S + i];
        }
    }
    sm_acc[tid] = acc;
    __syncthreads();
    if (tid < S)
        out[2*BSS + (b*S + tid)*S + j] += sm_acc[tid] + sm_acc[tid + 128];
}

// ---------------------------------------------------------------------------
extern "C" void kernel_launch(void* const* d_in, const int* in_sizes, int n_in,
                              void* d_out, int out_size)
{
    const float* s_const     = (const float*)d_in[0];
    const float* s_arg_begin = (const float*)d_in[1];
    const float* s_arg_end   = (const float*)d_in[2];
    const float* s_sib_be    = (const float*)d_in[3];
    const float* s_sib_eb    = (const float*)d_in[4];
    const float* s_sib_bb    = (const float*)d_in[5];
    const float* s_sib_ee    = (const float*)d_in[6];
    const float* s_cop_b     = (const float*)d_in[7];
    const float* s_cop_e     = (const float*)d_in[8];
    const float* s_grd_b     = (const float*)d_in[9];
    const float* s_grd_e     = (const float*)d_in[10];
    const float* s_split     = (const float*)d_in[11];
    const unsigned char* edge   = (const unsigned char*)d_in[12];
    const unsigned char* chartm = (const unsigned char*)d_in[13];
    float* out = (float*)d_out;

    k_detect<<<1, 1>>>((const unsigned int*)edge, (const unsigned int*)chartm);
    k_convert<<<(BSS + 255) / 256, 256>>>(edge, chartm);
    k_init<<<(BSS + 255) / 256, 256>>>(s_arg_begin, s_arg_end, s_const, out);

    for (int it = 0; it < 3; ++it) {
        k_sigmoid<<<(BSS + 255) / 256, 256>>>(out);
        k_main<<<B * S, 256>>>(s_sib_be, s_sib_eb, s_sib_bb, s_sib_ee,
                               s_cop_b, s_cop_e, s_grd_b, s_grd_e, s_split,
                               out);
        k_spanE<<<B * S, 256>>>(s_grd_e, out);
    }
}

// round 3
// speedup vs baseline: 1.6944x; 1.6944x over previous
#include <cuda_runtime.h>

#define B 4
#define S 128
#define SS (S*S)
#define BSS (B*S*S)

__device__ __align__(16) float g_qb[BSS], g_qe[BSS], g_qs[BSS];
__device__ __align__(16) float g_qbT[BSS], g_qeT[BSS], g_qsT[BSS];
__device__ unsigned char g_edge[BSS];
__device__ unsigned char g_chart[BSS];
__device__ int g_mode_e, g_mode_c;   // 0=uint8, 1=int32, 2=float32

// ---------------------------------------------------------------------------
// dtype sniffing (parallel): bool masks may arrive as uint8/int32/float32.
// ---------------------------------------------------------------------------
__global__ void k_detect(const unsigned int* __restrict__ me,
                         const unsigned int* __restrict__ mc)
{
    __shared__ int f[4];                // e_is01, e_isf, c_is01, c_isf
    const int tid = threadIdx.x;
    if (tid < 4) f[tid] = 1;
    __syncthreads();
    if (tid < 64) {
        unsigned v = me[tid];
        if (v != 0u && v != 1u)          atomicAnd(&f[0], 0);
        if (v != 0u && v != 0x3f800000u) atomicAnd(&f[1], 0);
    } else {
        unsigned v = mc[tid - 64];
        if (v != 0u && v != 1u)          atomicAnd(&f[2], 0);
        if (v != 0u && v != 0x3f800000u) atomicAnd(&f[3], 0);
    }
    __syncthreads();
    if (tid == 0) {
        g_mode_e = f[0] ? 1 : (f[1] ? 2 : 0);
        g_mode_c = f[2] ? 1 : (f[3] ? 2 : 0);
    }
}

__global__ void k_convert(const void* __restrict__ se, const void* __restrict__ sc)
{
    const int q = blockIdx.x * blockDim.x + threadIdx.x;   // quad index
    if (q * 4 >= BSS) return;
    const int me = g_mode_e, mc = g_mode_c;
    uchar4 e, c;
    if (me == 1)      { int4 v = ((const int4*)se)[q];
                        e = make_uchar4(v.x != 0, v.y != 0, v.z != 0, v.w != 0); }
    else if (me == 2) { float4 v = ((const float4*)se)[q];
                        e = make_uchar4(v.x != 0.f, v.y != 0.f, v.z != 0.f, v.w != 0.f); }
    else              { uchar4 v = ((const uchar4*)se)[q];
                        e = make_uchar4(v.x != 0, v.y != 0, v.z != 0, v.w != 0); }
    if (mc == 1)      { int4 v = ((const int4*)sc)[q];
                        c = make_uchar4(v.x != 0, v.y != 0, v.z != 0, v.w != 0); }
    else if (mc == 2) { float4 v = ((const float4*)sc)[q];
                        c = make_uchar4(v.x != 0.f, v.y != 0.f, v.z != 0.f, v.w != 0.f); }
    else              { uchar4 v = ((const uchar4*)sc)[q];
                        c = make_uchar4(v.x != 0, v.y != 0, v.z != 0, v.w != 0); }
    ((uchar4*)g_edge)[q]  = e;
    ((uchar4*)g_chart)[q] = c;
}

__global__ void k_init(const float4* __restrict__ sb, const float4* __restrict__ se,
                       const float4* __restrict__ sc, float4* __restrict__ out)
{
    const int q = blockIdx.x * blockDim.x + threadIdx.x;
    if (q * 4 >= BSS) return;
    out[q]             = sb[q];
    out[BSS/4 + q]     = se[q];
    out[2*(BSS/4) + q] = sc[q];
}

__device__ __forceinline__ float4 sig4(float4 v)
{
    return make_float4(1.f/(1.f+__expf(-v.x)), 1.f/(1.f+__expf(-v.y)),
                       1.f/(1.f+__expf(-v.z)), 1.f/(1.f+__expf(-v.w)));
}

__global__ void k_sigmoid(const float4* __restrict__ out)
{
    const int q = blockIdx.x * blockDim.x + threadIdx.x;
    if (q * 4 >= BSS) return;
    const int idx = q * 4;
    const int b = idx / SS;
    const int r = (idx / S) & (S - 1);
    const int c = idx & (S - 1);

    float4 vb = sig4(out[q]);
    float4 ve = sig4(out[BSS/4 + q]);
    float4 vs = sig4(out[2*(BSS/4) + q]);
    ((float4*)g_qb)[q] = vb;
    ((float4*)g_qe)[q] = ve;
    ((float4*)g_qs)[q] = vs;
    const int t0 = (b*S + c)*S + r;     // transposed base; columns c..c+3 -> rows
    g_qbT[t0]       = vb.x; g_qbT[t0 + S]   = vb.y;
    g_qbT[t0 + 2*S] = vb.z; g_qbT[t0 + 3*S] = vb.w;
    g_qeT[t0]       = ve.x; g_qeT[t0 + S]   = ve.y;
    g_qeT[t0 + 2*S] = ve.z; g_qeT[t0 + 3*S] = ve.w;
    g_qsT[t0]       = vs.x; g_qsT[t0 + S]   = vs.y;
    g_qsT[t0 + 2*S] = vs.z; g_qsT[t0 + 3*S] = vs.w;
}

// ---------------------------------------------------------------------------
// k_main: block = (b, i).
// ---------------------------------------------------------------------------
__global__ void __launch_bounds__(256) k_main(
    const float* __restrict__ t_be, const float* __restrict__ t_eb,
    const float* __restrict__ t_bb, const float* __restrict__ t_ee,
    const float* __restrict__ t_cb, const float* __restrict__ t_ce,
    const float* __restrict__ t_gb, const float* __restrict__ t_ge,
    const float* __restrict__ t_sp,
    float* __restrict__ out)
{
    const int b    = blockIdx.x >> 7;
    const int i    = blockIdx.x & 127;
    const int tid  = threadIdx.x;
    const int lane = tid & 31;
    const int warp = tid >> 5;

    __shared__ unsigned char sm_e[S], sm_ch[S], sm_c0[S];
    __shared__ float sm_qb[S], sm_qe[S], sm_qs[S], sm_qbT[S];
    __shared__ float sm_ab[S], sm_ae[S], sm_as[S];
    __shared__ float sm_span[256];
    __shared__ int lj_e[S], lj_s[S], lk[S];
    __shared__ int n_e, n_s, n_k;

    if (tid == 0) { n_e = 0; n_s = 0; n_k = 0; }
    __syncthreads();
    if (tid < S) {
        sm_ab[tid] = 0.f; sm_ae[tid] = 0.f; sm_as[tid] = 0.f;
        const unsigned char e  = g_edge[(b*S + i)*S + tid];
        const unsigned char ch = g_chart[(b*S + ((i + S - 1) & 127))*S + tid];
        const unsigned char c0 = g_chart[b*SS + tid];
        sm_e[tid] = e; sm_ch[tid] = ch; sm_c0[tid] = c0;
        const int q = (b*S + i)*S + tid;
        sm_qb[tid]  = g_qb[q];
        sm_qe[tid]  = g_qe[q];
        sm_qs[tid]  = g_qs[q];
        sm_qbT[tid] = g_qbT[q];
        if (e)        lj_e[atomicAdd(&n_e, 1)] = tid;
        if (ch && c0) lj_s[atomicAdd(&n_s, 1)] = tid;
        if (c0)       lk[atomicAdd(&n_k, 1)]  = tid;
    }
    __syncthreads();

    const int k0 = lane * 4;

    // ---- phase 1a: edge-masked terms, dense over compacted j-list ----
    for (int jj = warp; jj < n_e; jj += 8) {
        const int j = lj_e[jj];
        const int rowoff = ((b*S + i)*S + j)*S + k0;
        const int qoff   = (b*S + j)*S + k0;

        float a_be[4], a_eb[4], a_bb[4], a_ee[4], a_cb[4], a_ce[4];
        float a_gb[4] = {0,0,0,0}, a_ge[4] = {0,0,0,0};
        float qbTj[4], qeTj[4], qsj[4] = {0,0,0,0}, qsTj[4] = {0,0,0,0};
        *(float4*)a_be = *(const float4*)(t_be + rowoff);
        *(float4*)a_eb = *(const float4*)(t_eb + rowoff);
        *(float4*)a_bb = *(const float4*)(t_bb + rowoff);
        *(float4*)a_ee = *(const float4*)(t_ee + rowoff);
        *(float4*)a_cb = *(const float4*)(t_cb + rowoff);
        *(float4*)a_ce = *(const float4*)(t_ce + rowoff);
        *(float4*)qbTj = *(const float4*)(g_qbT + qoff);
        *(float4*)qeTj = *(const float4*)(g_qeT + qoff);
        // noncross (grd_b): needs j<=k and (j>=i || k<=i)
        if ((k0 + 3 >= j) && (j >= i || k0 <= i)) {
            *(float4*)a_gb = *(const float4*)(t_gb + rowoff);
            *(float4*)qsj  = *(const float4*)(g_qs + qoff);
        }
        // noncross swapped (grd_e): needs k<=j and (k>=i || j<=i)
        if ((k0 <= j) && (j <= i || k0 + 3 >= i)) {
            *(float4*)a_ge  = *(const float4*)(t_ge + rowoff);
            *(float4*)qsTj  = *(const float4*)(g_qsT + qoff);
        }

        float ab = 0.f, ae = 0.f;
        const float m_sw_row = (i != j) ? 1.f : 0.f;
        #pragma unroll
        for (int u = 0; u < 4; ++u) {
            const int k = k0 + u;
            const float e_ik = sm_e[k] ? 1.f : 0.f;
            const float m_wm = (i != k) ? e_ik : 0.f;
            const float m_2o = (j != k) ? m_wm : 0.f;
            const float m_nc = (j <= k && (j >= i || k <= i)) ? m_wm : 0.f;
            const float m_sw = m_sw_row * e_ik;
            const float m_ns = (k <= j && (k >= i || j <= i)) ? m_sw : 0.f;

            ab += m_wm * sm_qe[k] * a_be[u]
                + m_2o * (sm_qb[k] * a_bb[u] + qbTj[u] * a_cb[u])
                + m_nc * qsj[u] * a_gb[u];
            ae += m_sw * sm_qb[k] * a_eb[u]
                + m_2o * (sm_qe[k] * a_ee[u] + qeTj[u] * a_ce[u])
                + m_ns * qsTj[u] * a_ge[u];
        }
        #pragma unroll
        for (int o = 16; o; o >>= 1) {
            ab += __shfl_xor_sync(0xffffffffu, ab, o);
            ae += __shfl_xor_sync(0xffffffffu, ae, o);
        }
        if (lane == 0) { sm_ab[j] = ab; sm_ae[j] = ae; }
    }

    // ---- phase 1b: split term, dense over compacted span-j list ----
    for (int jj = warp; jj < n_s; jj += 8) {
        const int j = lj_s[jj];
        float a_sp[4];
        *(float4*)a_sp = *(const float4*)(t_sp + ((b*S + i)*S + j)*S + k0);
        const int mx = (i > j) ? i : j;
        float as_ = 0.f;
        #pragma unroll
        for (int u = 0; u < 4; ++u) {
            const int k = k0 + u;
            const float m = (sm_c0[k] && k != mx) ? 1.f : 0.f;
            as_ += m * sm_qs[k] * a_sp[u];
        }
        #pragma unroll
        for (int o = 16; o; o >>= 1)
            as_ += __shfl_xor_sync(0xffffffffu, as_, o);
        if (lane == 0) sm_as[j] = as_;
    }
    __syncthreads();

    // ---- phase 2: span_grd_b — dense gather over compacted c0-k list ----
    {
        const int j  = tid & 127;
        const int kh = tid >> 7;
        float acc = 0.f;
        if (sm_ch[j] && sm_c0[j]) {
            const int mx = (i > j) ? i : j;
            #pragma unroll 4
            for (int t = kh; t < n_k; t += 2) {
                const int k = lk[t];
                const float w = (!((i <= k) && (j >= k)) && (mx != k)) ? sm_qbT[k] : 0.f;
                acc += w * t_gb[((b*S + k)*S + i)*S + j];
            }
        }
        sm_span[tid] = acc;
    }
    __syncthreads();

    if (tid < S) {
        const int o = (b*S + i)*S + tid;
        out[o]         += sm_ab[tid];
        out[BSS + o]   += sm_ae[tid];
        out[2*BSS + o] += sm_as[tid] + sm_span[tid] + sm_span[tid + 128];
    }
}

// ---------------------------------------------------------------------------
// k_spanE: block = (b, j). base_s[b,i,j] += sum_k qe[b,k,j]*grd_e[b,k,j,i]*outside
// ---------------------------------------------------------------------------
__global__ void __launch_bounds__(256) k_spanE(
    const float* __restrict__ t_ge,
    float* __restrict__ out)
{
    const int b   = blockIdx.x >> 7;
    const int j   = blockIdx.x & 127;
    const int tid = threadIdx.x;

    __shared__ unsigned char sm_c0[S], sm_chc[S];
    __shared__ float sm_qeT[S];
    __shared__ float sm_acc[256];
    __shared__ int lk[S], n_k;

    if (tid == 0) n_k = 0;
    __syncthreads();
    if (tid < S) {
        const unsigned char c0 = g_chart[b*SS + tid];
        sm_c0[tid]  = c0;
        sm_chc[tid] = g_chart[(b*S + ((tid + S - 1) & 127))*S + j];
        sm_qeT[tid] = g_qeT[(b*S + j)*S + tid];
        if (c0) lk[atomicAdd(&n_k, 1)] = tid;
    }
    __syncthreads();
    if (!sm_c0[j]) return;   // block-uniform

    const int i  = tid & 127;
    const int kh = tid >> 7;
    float acc = 0.f;
    if (sm_chc[i]) {
        const int mx = (i > j) ? i : j;
        #pragma unroll 4
        for (int t = kh; t < n_k; t += 2) {
            const int k = lk[t];
            const float w = (!((i <= k) && (j >= k)) && (mx != k)) ? sm_qeT[k] : 0.f;
            acc += w * t_ge[((b*S + k)*S + j)*S + i];
        }
    }
    sm_acc[tid] = acc;
    __syncthreads();
    if (tid < S)
        out[2*BSS + (b*S + tid)*S + j] += sm_acc[tid] + sm_acc[tid + 128];
}

// ---------------------------------------------------------------------------
extern "C" void kernel_launch(void* const* d_in, const int* in_sizes, int n_in,
                              void* d_out, int out_size)
{
    const float* s_const     = (const float*)d_in[0];
    const float* s_arg_begin = (const float*)d_in[1];
    const float* s_arg_end   = (const float*)d_in[2];
    const float* s_sib_be    = (const float*)d_in[3];
    const float* s_sib_eb    = (const float*)d_in[4];
    const float* s_sib_bb    = (const float*)d_in[5];
    const float* s_sib_ee    = (const float*)d_in[6];
    const float* s_cop_b     = (const float*)d_in[7];
    const float* s_cop_e     = (const float*)d_in[8];
    const float* s_grd_b     = (const float*)d_in[9];
    const float* s_grd_e     = (const float*)d_in[10];
    const float* s_split     = (const float*)d_in[11];
    const void*  edge        = d_in[12];
    const void*  chartm      = d_in[13];
    float* out = (float*)d_out;

    const int q4 = BSS / 4;                       // 16384 quads
    k_detect<<<1, 128>>>((const unsigned int*)edge, (const unsigned int*)chartm);
    k_convert<<<q4 / 128, 128>>>(edge, chartm);
    k_init<<<q4 / 128, 128>>>((const float4*)s_arg_begin, (const float4*)s_arg_end,
                              (const float4*)s_const, (float4*)out);

    for (int it = 0; it < 3; ++it) {
        k_sigmoid<<<q4 / 128, 128>>>((const float4*)out);
        k_spanE<<<B * S, 256>>>(s_grd_e, out);     // before k_main so ncu -s5 lands on k_main
        k_main<<<B * S, 256>>>(s_sib_be, s_sib_eb, s_sib_bb, s_sib_ee,
                               s_cop_b, s_cop_e, s_grd_b, s_grd_e, s_split,
                               out);
    }
}